// round 1
// baseline (speedup 1.0000x reference)
#include <cuda_runtime.h>

#define NN 100000
#define NE 1600000
#define FD 128
#define NC 64

// Scratch (static device arrays — no allocation in kernel_launch)
__device__ float g_x0[NN * NC];
__device__ float g_x1[NN * NC];
__device__ int   g_deg[NN];
__device__ int   g_rowptr[NN + 1];
__device__ int   g_cursor[NN];
__device__ int   g_cols[NE];

__global__ void zero_deg_kernel() {
    int i = blockIdx.x * blockDim.x + threadIdx.x;
    if (i < NN) g_deg[i] = 0;
}

__global__ void hist_kernel(const int* __restrict__ dst) {
    int i = blockIdx.x * blockDim.x + threadIdx.x;
    if (i < NE) atomicAdd(&g_deg[dst[i]], 1);
}

// Single-block exclusive scan over g_deg -> g_rowptr (and cursor copy).
__global__ void scan_kernel() {
    __shared__ int part[1024];
    const int T = 1024;
    const int CH = (NN + T - 1) / T;  // 98
    int t = threadIdx.x;
    int base = t * CH;
    int s = 0;
    for (int i = 0; i < CH; i++) {
        int idx = base + i;
        if (idx < NN) s += g_deg[idx];
    }
    part[t] = s;
    __syncthreads();
    for (int off = 1; off < T; off <<= 1) {
        int v = (t >= off) ? part[t - off] : 0;
        __syncthreads();
        if (t >= off) part[t] += v;
        __syncthreads();
    }
    int run = (t == 0) ? 0 : part[t - 1];
    for (int i = 0; i < CH; i++) {
        int idx = base + i;
        if (idx < NN) {
            g_rowptr[idx] = run;
            g_cursor[idx] = run;
            run += g_deg[idx];
        } else if (idx == NN) {
            g_rowptr[NN] = run;
        }
    }
}

__global__ void scatter_kernel(const int* __restrict__ src, const int* __restrict__ dst) {
    int i = blockIdx.x * blockDim.x + threadIdx.x;
    if (i < NE) {
        int p = atomicAdd(&g_cursor[dst[i]], 1);
        g_cols[p] = src[i];
    }
}

// g_x0 = feat @ W^T ; out = c0 * g_x0 + bias   (fp32 FMA, W staged in smem)
// 256 threads: 32 nodes/block, 8 threads per node, each thread computes 8 outputs
// at columns c = (t&7) + 8j  -> conflict-free smem loads with stride-129 padding.
__global__ void gemm_kernel(const float* __restrict__ feat,
                            const float* __restrict__ W,
                            const float* __restrict__ bias,
                            float* __restrict__ out, float c0) {
    __shared__ float sW[NC * 129];
    int t = threadIdx.x;  // 256
    for (int i = t; i < NC * FD; i += 256) {
        int c = i >> 7;
        int k = i & 127;
        sW[c * 129 + k] = W[i];
    }
    __syncthreads();
    int nl = t >> 3;   // 0..31
    int cl = t & 7;
    int gn = blockIdx.x * 32 + nl;
    int gclamp = gn < NN ? gn : NN - 1;
    float acc[8];
#pragma unroll
    for (int j = 0; j < 8; j++) acc[j] = 0.f;
    const float* fr = feat + (size_t)gclamp * FD;
#pragma unroll 4
    for (int k = 0; k < FD; k++) {
        float f = __ldg(&fr[k]);
#pragma unroll
        for (int j = 0; j < 8; j++)
            acc[j] += f * sW[(cl + 8 * j) * 129 + k];
    }
    if (gn < NN) {
#pragma unroll
        for (int j = 0; j < 8; j++) {
            int c = cl + 8 * j;
            float v = acc[j];
            g_x0[(size_t)gn * NC + c] = v;
            out[(size_t)gn * NC + c] = c0 * v + __ldg(&bias[c]);
        }
    }
}

// One warp per dst node: y[n] = sum_{e in row n} x[cols[e]];  out[n] += ck*y[n]
__global__ void spmm_kernel(int dir, float ck, float* __restrict__ out) {
    int w = (blockIdx.x * blockDim.x + threadIdx.x) >> 5;
    int lane = threadIdx.x & 31;
    if (w >= NN) return;
    const float2* __restrict__ x = (const float2*)(dir ? g_x1 : g_x0);
    float2* __restrict__ y = (float2*)(dir ? g_x0 : g_x1);
    int start = __ldg(&g_rowptr[w]);
    int end = __ldg(&g_rowptr[w + 1]);
    float ax = 0.f, ay = 0.f;
    int e = start;
    for (; e + 4 <= end; e += 4) {
        int s0 = __ldg(&g_cols[e]);
        int s1 = __ldg(&g_cols[e + 1]);
        int s2 = __ldg(&g_cols[e + 2]);
        int s3 = __ldg(&g_cols[e + 3]);
        float2 v0 = __ldg(&x[s0 * 32 + lane]);
        float2 v1 = __ldg(&x[s1 * 32 + lane]);
        float2 v2 = __ldg(&x[s2 * 32 + lane]);
        float2 v3 = __ldg(&x[s3 * 32 + lane]);
        ax += (v0.x + v1.x) + (v2.x + v3.x);
        ay += (v0.y + v1.y) + (v2.y + v3.y);
    }
    for (; e < end; ++e) {
        float2 v = __ldg(&x[__ldg(&g_cols[e]) * 32 + lane]);
        ax += v.x;
        ay += v.y;
    }
    int off = w * 32 + lane;
    y[off] = make_float2(ax, ay);
    float2* __restrict__ o2 = (float2*)out;
    float2 o = o2[off];
    o.x += ck * ax;
    o.y += ck * ay;
    o2[off] = o;
}

extern "C" void kernel_launch(void* const* d_in, const int* in_sizes, int n_in,
                              void* d_out, int out_size) {
    const float* feat = (const float*)d_in[0];
    const float* W    = (const float*)d_in[1];
    const float* bias = (const float*)d_in[2];
    const int* esrc   = (const int*)d_in[3];
    const int* edst   = (const int*)d_in[4];
    float* out = (float*)d_out;

    // h_K = sum_k 0.95*8^{k-9} * A^k f0  +  0.05*(sum_k 8^{k-9}) * f0
    double ckd[8];
    double p = 1.0, csum = 0.0;
    for (int k = 8; k >= 1; --k) {
        p /= 8.0;
        ckd[k - 1] = 0.95 * p;
        csum += p;
    }
    float c0 = (float)(0.05 * csum);

    // Build CSR by dst
    zero_deg_kernel<<<(NN + 255) / 256, 256>>>();
    hist_kernel<<<(NE + 255) / 256, 256>>>(edst);
    scan_kernel<<<1, 1024>>>();
    scatter_kernel<<<(NE + 255) / 256, 256>>>(esrc, edst);

    // Project first: x0 = feat @ W^T; out = c0*x0 + bias
    gemm_kernel<<<(NN + 31) / 32, 256>>>(feat, W, bias, out, c0);

    // 8 SpMM iterations on 64-dim vectors, fused out-accumulation
    int warps = NN;
    int blocks = (warps * 32 + 255) / 256;
    for (int k = 0; k < 8; ++k) {
        spmm_kernel<<<blocks, 256>>>(k & 1, (float)ckd[k], out);
    }
}

// round 2
// speedup vs baseline: 1.6410x; 1.6410x over previous
#include <cuda_runtime.h>

#define NN 100000
#define NE 1600000
#define FD 128
#define NC 64
#define SCAN_B 391   // ceil(NN/256)

// Scratch (static device arrays — no allocation in kernel_launch)
__device__ float g_x0[NN * NC];
__device__ float g_x1[NN * NC];
__device__ int   g_deg[NN];
__device__ int   g_rowptr[NN + 1];
__device__ int   g_cursor[NN];
__device__ int   g_cols[NE];
__device__ int   g_bsum[512];
__device__ int   g_bpre[512];

__global__ void zero_deg_kernel() {
    int i = blockIdx.x * blockDim.x + threadIdx.x;
    if (i < NN) g_deg[i] = 0;
}

// int4-vectorized histogram: NE divisible by 4
__global__ void hist_kernel(const int* __restrict__ dst) {
    int i = blockIdx.x * blockDim.x + threadIdx.x;
    if (i < NE / 4) {
        int4 d = __ldg((const int4*)dst + i);
        atomicAdd(&g_deg[d.x], 1);
        atomicAdd(&g_deg[d.y], 1);
        atomicAdd(&g_deg[d.z], 1);
        atomicAdd(&g_deg[d.w], 1);
    }
}

// --- multi-block exclusive scan of g_deg -> g_rowptr / g_cursor ---
__global__ void scan1_kernel() {
    __shared__ int s[256];
    int i = blockIdx.x * 256 + threadIdx.x;
    s[threadIdx.x] = (i < NN) ? g_deg[i] : 0;
    __syncthreads();
#pragma unroll
    for (int off = 128; off > 0; off >>= 1) {
        if (threadIdx.x < off) s[threadIdx.x] += s[threadIdx.x + off];
        __syncthreads();
    }
    if (threadIdx.x == 0) g_bsum[blockIdx.x] = s[0];
}

__global__ void scan2_kernel() {
    __shared__ int s[512];
    int t = threadIdx.x;
    int orig = (t < SCAN_B) ? g_bsum[t] : 0;
    s[t] = orig;
    __syncthreads();
#pragma unroll
    for (int off = 1; off < 512; off <<= 1) {
        int v = (t >= off) ? s[t - off] : 0;
        __syncthreads();
        s[t] += v;
        __syncthreads();
    }
    if (t < SCAN_B) g_bpre[t] = s[t] - orig;  // exclusive prefix of block sums
}

__global__ void scan3_kernel() {
    __shared__ int s[256];
    int t = threadIdx.x;
    int i = blockIdx.x * 256 + t;
    int orig = (i < NN) ? g_deg[i] : 0;
    s[t] = orig;
    __syncthreads();
#pragma unroll
    for (int off = 1; off < 256; off <<= 1) {
        int v = (t >= off) ? s[t - off] : 0;
        __syncthreads();
        s[t] += v;
        __syncthreads();
    }
    if (i < NN) {
        int excl = s[t] - orig + g_bpre[blockIdx.x];
        g_rowptr[i] = excl;
        g_cursor[i] = excl;
        if (i == NN - 1) g_rowptr[NN] = excl + orig;
    }
}

// int4-vectorized scatter
__global__ void scatter_kernel(const int* __restrict__ src, const int* __restrict__ dst) {
    int i = blockIdx.x * blockDim.x + threadIdx.x;
    if (i < NE / 4) {
        int4 d = __ldg((const int4*)dst + i);
        int4 s = __ldg((const int4*)src + i);
        int p;
        p = atomicAdd(&g_cursor[d.x], 1); g_cols[p] = s.x;
        p = atomicAdd(&g_cursor[d.y], 1); g_cols[p] = s.y;
        p = atomicAdd(&g_cursor[d.z], 1); g_cols[p] = s.z;
        p = atomicAdd(&g_cursor[d.w], 1); g_cols[p] = s.w;
    }
}

// FMA-blocked GEMM: x0 = feat @ W^T ; out = c0*x0 + bias
// Block = 128 threads, tile = 128 nodes x 64 cols; thread = 8 nodes x 8 cols.
__global__ __launch_bounds__(128) void gemm_kernel(
    const float* __restrict__ feat, const float* __restrict__ W,
    const float* __restrict__ bias, float* __restrict__ out, float c0)
{
    __shared__ float sF[16][128];
    __shared__ float sW[16][64];
    int t = threadIdx.x;
    int gi = t >> 3;   // 0..15: node group, nodes gi*8 .. gi*8+7
    int gj = t & 7;    // 0..7 : col group, cols gj*8 .. gj*8+7
    int base = blockIdx.x * 128;

    float acc[8][8];
#pragma unroll
    for (int s = 0; s < 8; s++)
#pragma unroll
        for (int r = 0; r < 8; r++) acc[s][r] = 0.f;

    int myrow = base + t;
    int rowc = (myrow < NN) ? myrow : (NN - 1);
    const float4* frow = (const float4*)(feat + (size_t)rowc * FD);
    int wc = t & 63;       // col this thread stages
    int wh = t >> 6;       // which 8-k half

    for (int kc = 0; kc < 8; ++kc) {
        __syncthreads();
        // stage feat chunk: 16 k-values for node (base+t)
#pragma unroll
        for (int u = 0; u < 4; ++u) {
            float4 f = __ldg(&frow[kc * 4 + u]);
            sF[u * 4 + 0][t] = f.x;
            sF[u * 4 + 1][t] = f.y;
            sF[u * 4 + 2][t] = f.z;
            sF[u * 4 + 3][t] = f.w;
        }
        // stage W chunk: col wc, k = kc*16 + wh*8 .. +7
        const float4* wrow = (const float4*)(W + (size_t)wc * FD + kc * 16 + wh * 8);
        float4 w0 = __ldg(&wrow[0]);
        float4 w1 = __ldg(&wrow[1]);
        sW[wh * 8 + 0][wc] = w0.x; sW[wh * 8 + 1][wc] = w0.y;
        sW[wh * 8 + 2][wc] = w0.z; sW[wh * 8 + 3][wc] = w0.w;
        sW[wh * 8 + 4][wc] = w1.x; sW[wh * 8 + 5][wc] = w1.y;
        sW[wh * 8 + 6][wc] = w1.z; sW[wh * 8 + 7][wc] = w1.w;
        __syncthreads();
#pragma unroll
        for (int kk = 0; kk < 16; ++kk) {
            float4 f0 = *(const float4*)&sF[kk][gi * 8];
            float4 f1 = *(const float4*)&sF[kk][gi * 8 + 4];
            float4 v0 = *(const float4*)&sW[kk][gj * 8];
            float4 v1 = *(const float4*)&sW[kk][gj * 8 + 4];
            float fv[8] = {f0.x, f0.y, f0.z, f0.w, f1.x, f1.y, f1.z, f1.w};
            float wv[8] = {v0.x, v0.y, v0.z, v0.w, v1.x, v1.y, v1.z, v1.w};
#pragma unroll
            for (int s = 0; s < 8; s++)
#pragma unroll
                for (int r = 0; r < 8; r++) acc[s][r] += fv[s] * wv[r];
        }
    }

    float bv[8];
#pragma unroll
    for (int r = 0; r < 8; r++) bv[r] = __ldg(&bias[gj * 8 + r]);

#pragma unroll
    for (int s = 0; s < 8; s++) {
        int node = base + gi * 8 + s;
        if (node < NN) {
            float4 xa = make_float4(acc[s][0], acc[s][1], acc[s][2], acc[s][3]);
            float4 xb = make_float4(acc[s][4], acc[s][5], acc[s][6], acc[s][7]);
            float* xp = g_x0 + (size_t)node * NC + gj * 8;
            *(float4*)(xp)     = xa;
            *(float4*)(xp + 4) = xb;
            float4 oa = make_float4(c0 * acc[s][0] + bv[0], c0 * acc[s][1] + bv[1],
                                    c0 * acc[s][2] + bv[2], c0 * acc[s][3] + bv[3]);
            float4 ob = make_float4(c0 * acc[s][4] + bv[4], c0 * acc[s][5] + bv[5],
                                    c0 * acc[s][6] + bv[6], c0 * acc[s][7] + bv[7]);
            float* op = out + (size_t)node * NC + gj * 8;
            *(float4*)(op)     = oa;
            *(float4*)(op + 4) = ob;
        }
    }
}

// One warp per dst node: y[n] = sum_{e in row n} x[cols[e]];  out[n] += ck*y[n]
__global__ void spmm_kernel(int dir, float ck, float* __restrict__ out, int write_y) {
    int w = (blockIdx.x * blockDim.x + threadIdx.x) >> 5;
    int lane = threadIdx.x & 31;
    if (w >= NN) return;
    const float2* __restrict__ x = (const float2*)(dir ? g_x1 : g_x0);
    float2* __restrict__ y = (float2*)(dir ? g_x0 : g_x1);
    int start = __ldg(&g_rowptr[w]);
    int end = __ldg(&g_rowptr[w + 1]);
    float ax = 0.f, ay = 0.f;
    int e = start;
    // main loop: MLP 8
    for (; e + 8 <= end; e += 8) {
        int s[8];
#pragma unroll
        for (int u = 0; u < 8; u++) s[u] = __ldg(&g_cols[e + u]);
        float2 v[8];
#pragma unroll
        for (int u = 0; u < 8; u++) v[u] = __ldg(&x[s[u] * 32 + lane]);
#pragma unroll
        for (int u = 0; u < 8; u++) { ax += v[u].x; ay += v[u].y; }
    }
    // tail: MLP 4
    if (e + 4 <= end) {
        int s[4];
#pragma unroll
        for (int u = 0; u < 4; u++) s[u] = __ldg(&g_cols[e + u]);
        float2 v[4];
#pragma unroll
        for (int u = 0; u < 4; u++) v[u] = __ldg(&x[s[u] * 32 + lane]);
#pragma unroll
        for (int u = 0; u < 4; u++) { ax += v[u].x; ay += v[u].y; }
        e += 4;
    }
    for (; e < end; ++e) {
        float2 v = __ldg(&x[__ldg(&g_cols[e]) * 32 + lane]);
        ax += v.x; ay += v.y;
    }
    int off = w * 32 + lane;
    if (write_y) y[off] = make_float2(ax, ay);
    float2* __restrict__ o2 = (float2*)out;
    float2 o = o2[off];
    o.x += ck * ax;
    o.y += ck * ay;
    o2[off] = o;
}

extern "C" void kernel_launch(void* const* d_in, const int* in_sizes, int n_in,
                              void* d_out, int out_size) {
    const float* feat = (const float*)d_in[0];
    const float* W    = (const float*)d_in[1];
    const float* bias = (const float*)d_in[2];
    const int* esrc   = (const int*)d_in[3];
    const int* edst   = (const int*)d_in[4];
    float* out = (float*)d_out;

    // h_K = sum_k 0.95*8^{k-9} * A^k f0  +  0.05*(sum_k 8^{k-9}) * f0
    double ckd[8];
    double p = 1.0, csum = 0.0;
    for (int k = 8; k >= 1; --k) {
        p /= 8.0;
        ckd[k - 1] = 0.95 * p;
        csum += p;
    }
    float c0 = (float)(0.05 * csum);

    // Build CSR by dst
    zero_deg_kernel<<<(NN + 255) / 256, 256>>>();
    hist_kernel<<<(NE / 4 + 255) / 256, 256>>>(edst);
    scan1_kernel<<<SCAN_B, 256>>>();
    scan2_kernel<<<1, 512>>>();
    scan3_kernel<<<SCAN_B, 256>>>();
    scatter_kernel<<<(NE / 4 + 255) / 256, 256>>>(esrc, edst);

    // Project first: x0 = feat @ W^T; out = c0*x0 + bias
    gemm_kernel<<<(NN + 127) / 128, 128>>>(feat, W, bias, out, c0);

    // 8 SpMM iterations on 64-dim vectors, fused out-accumulation
    int blocks = (NN * 32 + 255) / 256;
    for (int k = 0; k < 8; ++k) {
        spmm_kernel<<<blocks, 256>>>(k & 1, (float)ckd[k], out, (k < 7) ? 1 : 0);
    }
}

// round 3
// speedup vs baseline: 1.9327x; 1.1778x over previous
#include <cuda_runtime.h>
#include <cuda_fp16.h>

#define NN 100000
#define NE 1600000
#define FD 128
#define NC 64
#define SCAN_B 391   // ceil(NN/256)

// Scratch (static device arrays — no allocation in kernel_launch)
__device__ __half2 g_x0h[NN * 32];   // x0 (projected feat), fp16, std ~1
__device__ __half2 g_sA[NN * 32];    // ping
__device__ __half2 g_sB[NN * 32];    // pong
__device__ int   g_deg[NN];
__device__ int   g_rowptr[NN + 1];
__device__ int   g_cursor[NN];
__device__ int   g_cols[NE];
__device__ int   g_bsum[512];
__device__ int   g_bpre[512];

__global__ void zero_deg_kernel() {
    int i = blockIdx.x * blockDim.x + threadIdx.x;
    if (i < NN) g_deg[i] = 0;
}

// int4-vectorized histogram (NE divisible by 4)
__global__ void hist_kernel(const int* __restrict__ dst) {
    int i = blockIdx.x * blockDim.x + threadIdx.x;
    if (i < NE / 4) {
        int4 d = __ldg((const int4*)dst + i);
        atomicAdd(&g_deg[d.x], 1);
        atomicAdd(&g_deg[d.y], 1);
        atomicAdd(&g_deg[d.z], 1);
        atomicAdd(&g_deg[d.w], 1);
    }
}

// --- multi-block exclusive scan of g_deg -> g_rowptr / g_cursor ---
__global__ void scan1_kernel() {
    __shared__ int s[256];
    int i = blockIdx.x * 256 + threadIdx.x;
    s[threadIdx.x] = (i < NN) ? g_deg[i] : 0;
    __syncthreads();
#pragma unroll
    for (int off = 128; off > 0; off >>= 1) {
        if (threadIdx.x < off) s[threadIdx.x] += s[threadIdx.x + off];
        __syncthreads();
    }
    if (threadIdx.x == 0) g_bsum[blockIdx.x] = s[0];
}

__global__ void scan2_kernel() {
    __shared__ int s[512];
    int t = threadIdx.x;
    int orig = (t < SCAN_B) ? g_bsum[t] : 0;
    s[t] = orig;
    __syncthreads();
#pragma unroll
    for (int off = 1; off < 512; off <<= 1) {
        int v = (t >= off) ? s[t - off] : 0;
        __syncthreads();
        s[t] += v;
        __syncthreads();
    }
    if (t < SCAN_B) g_bpre[t] = s[t] - orig;
}

__global__ void scan3_kernel() {
    __shared__ int s[256];
    int t = threadIdx.x;
    int i = blockIdx.x * 256 + t;
    int orig = (i < NN) ? g_deg[i] : 0;
    s[t] = orig;
    __syncthreads();
#pragma unroll
    for (int off = 1; off < 256; off <<= 1) {
        int v = (t >= off) ? s[t - off] : 0;
        __syncthreads();
        s[t] += v;
        __syncthreads();
    }
    if (i < NN) {
        int excl = s[t] - orig + g_bpre[blockIdx.x];
        g_rowptr[i] = excl;
        g_cursor[i] = excl;
        if (i == NN - 1) g_rowptr[NN] = excl + orig;
    }
}

// int4-vectorized scatter
__global__ void scatter_kernel(const int* __restrict__ src, const int* __restrict__ dst) {
    int i = blockIdx.x * blockDim.x + threadIdx.x;
    if (i < NE / 4) {
        int4 d = __ldg((const int4*)dst + i);
        int4 s = __ldg((const int4*)src + i);
        int p;
        p = atomicAdd(&g_cursor[d.x], 1); g_cols[p] = s.x;
        p = atomicAdd(&g_cursor[d.y], 1); g_cols[p] = s.y;
        p = atomicAdd(&g_cursor[d.z], 1); g_cols[p] = s.z;
        p = atomicAdd(&g_cursor[d.w], 1); g_cols[p] = s.w;
    }
}

// FMA-blocked GEMM: x0h = fp16(feat @ W^T)
// Block = 128 threads, tile = 128 nodes x 64 cols; thread = 8 nodes x 8 cols.
__global__ __launch_bounds__(128) void gemm_kernel(
    const float* __restrict__ feat, const float* __restrict__ W)
{
    __shared__ float sF[16][128];
    __shared__ float sW[16][64];
    int t = threadIdx.x;
    int gi = t >> 3;   // 0..15: node group
    int gj = t & 7;    // 0..7 : col group
    int base = blockIdx.x * 128;

    float acc[8][8];
#pragma unroll
    for (int s = 0; s < 8; s++)
#pragma unroll
        for (int r = 0; r < 8; r++) acc[s][r] = 0.f;

    int myrow = base + t;
    int rowc = (myrow < NN) ? myrow : (NN - 1);
    const float4* frow = (const float4*)(feat + (size_t)rowc * FD);
    int wc = t & 63;
    int wh = t >> 6;

    for (int kc = 0; kc < 8; ++kc) {
        __syncthreads();
#pragma unroll
        for (int u = 0; u < 4; ++u) {
            float4 f = __ldg(&frow[kc * 4 + u]);
            sF[u * 4 + 0][t] = f.x;
            sF[u * 4 + 1][t] = f.y;
            sF[u * 4 + 2][t] = f.z;
            sF[u * 4 + 3][t] = f.w;
        }
        const float4* wrow = (const float4*)(W + (size_t)wc * FD + kc * 16 + wh * 8);
        float4 w0 = __ldg(&wrow[0]);
        float4 w1 = __ldg(&wrow[1]);
        sW[wh * 8 + 0][wc] = w0.x; sW[wh * 8 + 1][wc] = w0.y;
        sW[wh * 8 + 2][wc] = w0.z; sW[wh * 8 + 3][wc] = w0.w;
        sW[wh * 8 + 4][wc] = w1.x; sW[wh * 8 + 5][wc] = w1.y;
        sW[wh * 8 + 6][wc] = w1.z; sW[wh * 8 + 7][wc] = w1.w;
        __syncthreads();
#pragma unroll
        for (int kk = 0; kk < 16; ++kk) {
            float4 f0 = *(const float4*)&sF[kk][gi * 8];
            float4 f1 = *(const float4*)&sF[kk][gi * 8 + 4];
            float4 v0 = *(const float4*)&sW[kk][gj * 8];
            float4 v1 = *(const float4*)&sW[kk][gj * 8 + 4];
            float fv[8] = {f0.x, f0.y, f0.z, f0.w, f1.x, f1.y, f1.z, f1.w};
            float wv[8] = {v0.x, v0.y, v0.z, v0.w, v1.x, v1.y, v1.z, v1.w};
#pragma unroll
            for (int s = 0; s < 8; s++)
#pragma unroll
                for (int r = 0; r < 8; r++) acc[s][r] += fv[s] * wv[r];
        }
    }

#pragma unroll
    for (int s = 0; s < 8; s++) {
        int node = base + gi * 8 + s;
        if (node < NN) {
            __half2 hv[4];
#pragma unroll
            for (int q = 0; q < 4; q++)
                hv[q] = __float22half2_rn(make_float2(acc[s][2 * q], acc[s][2 * q + 1]));
            // cols gj*8 .. gj*8+7  ->  half2 index gj*4 .. gj*4+3 (16B aligned)
            *(uint4*)(g_x0h + (size_t)node * 32 + gj * 4) = *(uint4*)hv;
        }
    }
}

// Horner SpMM step: dst[n] = fp16( gs * sum_{e in row n} src[cols[e]] + bi * x0h[n] )
// One warp per dst node; each lane owns one half2 (2 feature cols).
__global__ void spmm_kernel(const __half2* __restrict__ x, __half2* __restrict__ y,
                            float gs, float bi) {
    int w = (blockIdx.x * blockDim.x + threadIdx.x) >> 5;
    int lane = threadIdx.x & 31;
    if (w >= NN) return;
    int start = __ldg(&g_rowptr[w]);
    int end = __ldg(&g_rowptr[w + 1]);
    float ax = 0.f, ay = 0.f;
    int e = start;
    for (; e + 8 <= end; e += 8) {
        int s[8];
#pragma unroll
        for (int u = 0; u < 8; u++) s[u] = __ldg(&g_cols[e + u]);
        __half2 v[8];
#pragma unroll
        for (int u = 0; u < 8; u++) v[u] = __ldg(&x[s[u] * 32 + lane]);
#pragma unroll
        for (int u = 0; u < 8; u++) { float2 f = __half22float2(v[u]); ax += f.x; ay += f.y; }
    }
    if (e + 4 <= end) {
        int s[4];
#pragma unroll
        for (int u = 0; u < 4; u++) s[u] = __ldg(&g_cols[e + u]);
        __half2 v[4];
#pragma unroll
        for (int u = 0; u < 4; u++) v[u] = __ldg(&x[s[u] * 32 + lane]);
#pragma unroll
        for (int u = 0; u < 4; u++) { float2 f = __half22float2(v[u]); ax += f.x; ay += f.y; }
        e += 4;
    }
    for (; e < end; ++e) {
        float2 f = __half22float2(__ldg(&x[__ldg(&g_cols[e]) * 32 + lane]));
        ax += f.x; ay += f.y;
    }
    int off = w * 32 + lane;
    float2 x0 = __half22float2(__ldg(&g_x0h[off]));
    y[off] = __float22half2_rn(make_float2(gs * ax + bi * x0.x, gs * ay + bi * x0.y));
}

// Final SpMM: out[n] = gs * sum src[cols[e]] + c0 * x0h[n] + bias  (fp32 out)
__global__ void spmm_last_kernel(const __half2* __restrict__ x, float* __restrict__ out,
                                 const float* __restrict__ bias, float gs, float c0) {
    int w = (blockIdx.x * blockDim.x + threadIdx.x) >> 5;
    int lane = threadIdx.x & 31;
    if (w >= NN) return;
    int start = __ldg(&g_rowptr[w]);
    int end = __ldg(&g_rowptr[w + 1]);
    float ax = 0.f, ay = 0.f;
    int e = start;
    for (; e + 8 <= end; e += 8) {
        int s[8];
#pragma unroll
        for (int u = 0; u < 8; u++) s[u] = __ldg(&g_cols[e + u]);
        __half2 v[8];
#pragma unroll
        for (int u = 0; u < 8; u++) v[u] = __ldg(&x[s[u] * 32 + lane]);
#pragma unroll
        for (int u = 0; u < 8; u++) { float2 f = __half22float2(v[u]); ax += f.x; ay += f.y; }
    }
    for (; e < end; ++e) {
        float2 f = __half22float2(__ldg(&x[__ldg(&g_cols[e]) * 32 + lane]));
        ax += f.x; ay += f.y;
    }
    int off = w * 32 + lane;
    float2 x0 = __half22float2(__ldg(&g_x0h[off]));
    float2 b = __ldg((const float2*)bias + lane);
    float2 o = make_float2(gs * ax + c0 * x0.x + b.x,
                           gs * ay + c0 * x0.y + b.y);
    *((float2*)out + off) = o;
}

extern "C" void kernel_launch(void* const* d_in, const int* in_sizes, int n_in,
                              void* d_out, int out_size) {
    const float* feat = (const float*)d_in[0];
    const float* W    = (const float*)d_in[1];
    const float* bias = (const float*)d_in[2];
    const int* esrc   = (const int*)d_in[3];
    const int* edst   = (const int*)d_in[4];
    float* out = (float*)d_out;

    // h = sum_{k=1..8} c_k A^k x0 + c0 x0,  c_k = 0.95*8^{k-9}, c0 = 0.05*sum(8^{k-9})
    double c[9];
    double p = 1.0, csum = 0.0;
    for (int k = 8; k >= 1; --k) {
        p /= 8.0;
        c[k] = 0.95 * p;
        csum += p;
    }
    double c0 = 0.05 * csum;

    // Horner with per-hop 4x rescale: stored S_j = (s0 * 4^{-j}) * v_j,
    // v_1 = c8*x0, v_{j+1} = A v_j + c_{8-j} x0, out = A v_8 + c0 x0 + bias.
    // s0 chosen so S_1 = 2*x0 (std ~2, fp16-safe for all hops).
    double s0 = 8.0 / c[8];
    // j=1 reads x0h directly: S_2 = (s0*4^-2*c8)*A x0h + (s0*4^-2*c7)*x0h
    // general j: S_{j+1} = 0.25*A S_j + (s0*4^{-(j+1)}*c_{8-j})*x0h
    // last: out = (4^8/s0)*A S_8 + c0*x0h + bias

    // Build CSR by dst
    zero_deg_kernel<<<(NN + 255) / 256, 256>>>();
    hist_kernel<<<(NE / 4 + 255) / 256, 256>>>(edst);
    scan1_kernel<<<SCAN_B, 256>>>();
    scan2_kernel<<<1, 512>>>();
    scan3_kernel<<<SCAN_B, 256>>>();
    scatter_kernel<<<(NE / 4 + 255) / 256, 256>>>(esrc, edst);

    // Project first: x0h = fp16(feat @ W^T)
    gemm_kernel<<<(NN + 127) / 128, 128>>>(feat, W);

    int blocks = (NN * 32 + 255) / 256;

    __half2* x0hp; cudaGetSymbolAddress((void**)&x0hp, g_x0h);
    __half2* sAp;  cudaGetSymbolAddress((void**)&sAp, g_sA);
    __half2* sBp;  cudaGetSymbolAddress((void**)&sBp, g_sB);

    // j = 1: src = x0h (S_1 = 2*x0h folded into gs), dst = sA
    {
        double gs = s0 * (1.0 / 16.0) * c[8];        // = 0.5
        double bi = s0 * (1.0 / 16.0) * c[7];
        spmm_kernel<<<blocks, 256>>>(x0hp, sAp, (float)gs, (float)bi);
    }
    // j = 2..7
    double scale = 1.0 / 16.0;                        // 4^{-(j+1)} tracker, j=1 used 4^-2
    __half2* cur = sAp; __half2* nxt = sBp;
    for (int j = 2; j <= 7; ++j) {
        scale *= 0.25;                                // 4^{-(j+1)}
        double bi = s0 * scale * c[8 - j];
        spmm_kernel<<<blocks, 256>>>(cur, nxt, 0.25f, (float)bi);
        __half2* t = cur; cur = nxt; nxt = t;
    }
    // j = 8: out = (4^8/s0) * A S_8 + c0*x0h + bias
    {
        double gs = 65536.0 / s0;
        spmm_last_kernel<<<blocks, 256>>>(cur, out, bias, (float)gs, (float)c0);
    }
}